// round 1
// baseline (speedup 1.0000x reference)
#include <cuda_runtime.h>

#define G   16      // B*H
#define NSEQ 4096
#define DD  64
#define EE  64
#define CC  128     // chunk
#define NC  32      // chunks per sequence

// Scratch: exclusive-prefix KV states and k prefix sums (written pass1, scanned pass2)
__device__ __align__(16) float g_S[2ull * G * NC * DD * EE];     // 16 MB
__device__ __align__(16) float g_ksum[2ull * G * NC * DD];       // 256 KB

// ---------------------------------------------------------------------------
// Pass 1: per (chunk c, group g, map m) compute S_c[d][e] = sum_j k[j][d]*v[j][e]
// and ksum_c[d] = sum_j k[j][d].
// ---------------------------------------------------------------------------
__global__ __launch_bounds__(256) void pass1_kernel(const float* __restrict__ k1g,
                                                    const float* __restrict__ k2g,
                                                    const float* __restrict__ vg) {
    extern __shared__ float sm[];
    float* ks = sm;             // 128*64
    float* vs = sm + CC * DD;   // 128*64
    const int c = blockIdx.x, g = blockIdx.y, m = blockIdx.z;
    const int tid = threadIdx.x;
    const size_t cbase = ((size_t)g * NSEQ + (size_t)c * CC) * DD;
    const float* kp = (m ? k2g : k1g) + cbase;
    const float* vp = vg + cbase;

    #pragma unroll
    for (int u = 0; u < (CC * DD / 4) / 256; u++) {
        int idx = u * 256 + tid;
        ((float4*)ks)[idx] = ((const float4*)kp)[idx];
        ((float4*)vs)[idx] = ((const float4*)vp)[idx];
    }
    __syncthreads();

    const int d0 = (tid >> 4) * 4, e0 = (tid & 15) * 4;
    float acc[4][4];
    #pragma unroll
    for (int a = 0; a < 4; a++)
        #pragma unroll
        for (int b = 0; b < 4; b++) acc[a][b] = 0.f;

    #pragma unroll 4
    for (int j = 0; j < CC; j++) {
        float4 kk = *(const float4*)&ks[j * DD + d0];
        float4 vv = *(const float4*)&vs[j * DD + e0];
        acc[0][0] += kk.x * vv.x; acc[0][1] += kk.x * vv.y; acc[0][2] += kk.x * vv.z; acc[0][3] += kk.x * vv.w;
        acc[1][0] += kk.y * vv.x; acc[1][1] += kk.y * vv.y; acc[1][2] += kk.y * vv.z; acc[1][3] += kk.y * vv.w;
        acc[2][0] += kk.z * vv.x; acc[2][1] += kk.z * vv.y; acc[2][2] += kk.z * vv.z; acc[2][3] += kk.z * vv.w;
        acc[3][0] += kk.w * vv.x; acc[3][1] += kk.w * vv.y; acc[3][2] += kk.w * vv.z; acc[3][3] += kk.w * vv.w;
    }

    float* Sp = &g_S[(((size_t)m * G + g) * NC + c) * (size_t)(DD * EE)];
    #pragma unroll
    for (int dd = 0; dd < 4; dd++) {
        float4 r = make_float4(acc[dd][0], acc[dd][1], acc[dd][2], acc[dd][3]);
        *(float4*)&Sp[(d0 + dd) * EE + e0] = r;
    }
    if (tid < DD) {
        float s = 0.f;
        #pragma unroll 4
        for (int j = 0; j < CC; j++) s += ks[j * DD + tid];
        g_ksum[(((size_t)m * G + g) * NC + c) * DD + tid] = s;
    }
}

// ---------------------------------------------------------------------------
// Pass 2: in-place EXCLUSIVE prefix sum over the 32 chunks (per map, group).
// ---------------------------------------------------------------------------
__global__ __launch_bounds__(256) void pass2_kernel() {
    const int g = blockIdx.x, m = blockIdx.y, tid = threadIdx.x;
    float* base = &g_S[(((size_t)m * G + g) * NC) * (size_t)(DD * EE)];
    float run[16];
    #pragma unroll
    for (int u = 0; u < 16; u++) run[u] = 0.f;
    for (int c = 0; c < NC; c++) {
        float* p = base + (size_t)c * (DD * EE);
        #pragma unroll
        for (int u = 0; u < 16; u++) {
            int idx = u * 256 + tid;
            float t = p[idx];
            p[idx] = run[u];
            run[u] += t;
        }
    }
    if (tid < DD) {
        float r = 0.f;
        float* kb = &g_ksum[(((size_t)m * G + g) * NC) * DD];
        for (int c = 0; c < NC; c++) {
            float t = kb[c * DD + tid];
            kb[c * DD + tid] = r;
            r += t;
        }
    }
}

// ---------------------------------------------------------------------------
// Pass 3: per (chunk, group): combined masked scores T, intra+inter numerator,
// denominator from row sums of T, final divide, write out.
// Smem layout (floats):
//   T    [0      .. 16384)   128x128 combined masked scores
//   Q1   [16384  .. 24576)
//   Q2   [24576  .. 32768)
//   X    [32768  .. 49152)   stage A: K1(8192)+K2(8192); stage B: V(8192)+S1(4096)+S2(4096)
//   DEN  [49152  .. 51200)   128 rows x 16 j-group partials
//   DINV [51200  .. 51328)
//   KP1  [51328  .. 51392)   exclusive k prefix (map 0)
//   KP2  [51392  .. 51456)
// ---------------------------------------------------------------------------
#define OFF_T    0
#define OFF_Q1   16384
#define OFF_Q2   24576
#define OFF_X    32768
#define OFF_X2   40960
#define OFF_X3   45056
#define OFF_DEN  49152
#define OFF_DINV 51200
#define OFF_KP1  51328
#define OFF_KP2  51392
#define SMEM3_FLOATS 51456
#define SMEM3_BYTES (SMEM3_FLOATS * 4)

__global__ __launch_bounds__(256) void pass3_kernel(const float* __restrict__ q1g,
                                                    const float* __restrict__ q2g,
                                                    const float* __restrict__ k1g,
                                                    const float* __restrict__ k2g,
                                                    const float* __restrict__ vg,
                                                    float* __restrict__ outg) {
    extern __shared__ float sm[];
    const int c = blockIdx.x, g = blockIdx.y, tid = threadIdx.x;
    const size_t cbase = ((size_t)g * NSEQ + (size_t)c * CC) * DD;

    float* T   = sm + OFF_T;
    float* Q1  = sm + OFF_Q1;
    float* Q2  = sm + OFF_Q2;
    float* K1  = sm + OFF_X;
    float* K2  = sm + OFF_X2;
    float* V   = sm + OFF_X;    // aliases K1 after stage A
    float* S1  = sm + OFF_X2;   // aliases K2 after stage A
    float* S2  = sm + OFF_X3;
    float* DEN = sm + OFF_DEN;
    float* DNV = sm + OFF_DINV;
    float* KP1 = sm + OFF_KP1;
    float* KP2 = sm + OFF_KP2;

    // ---- load q1,q2,k1,k2 chunks + kpre vectors ----
    #pragma unroll
    for (int u = 0; u < 8; u++) {
        int idx = u * 256 + tid;
        ((float4*)Q1)[idx] = ((const float4*)(q1g + cbase))[idx];
        ((float4*)Q2)[idx] = ((const float4*)(q2g + cbase))[idx];
        ((float4*)K1)[idx] = ((const float4*)(k1g + cbase))[idx];
        ((float4*)K2)[idx] = ((const float4*)(k2g + cbase))[idx];
    }
    if (tid < DD) {
        KP1[tid] = g_ksum[(((size_t)0 * G + g) * NC + c) * DD + tid];
        KP2[tid] = g_ksum[(((size_t)1 * G + g) * NC + c) * DD + tid];
    }
    __syncthreads();

    const int ig = tid >> 4, jg = tid & 15;
    const int i0 = ig * 8, j0 = jg * 8;

    // ---- Stage A: T[i][j] = q1_i.k1_j + q2_i.k2_j (8x8 per thread) ----
    float acc[8][8];
    #pragma unroll
    for (int a = 0; a < 8; a++)
        #pragma unroll
        for (int b = 0; b < 8; b++) acc[a][b] = 0.f;
    float dq[8];
    #pragma unroll
    for (int a = 0; a < 8; a++) dq[a] = 0.f;

    #pragma unroll 1
    for (int m = 0; m < 2; m++) {
        const float* Q  = m ? Q2  : Q1;
        const float* K  = m ? K2  : K1;
        const float* KP = m ? KP2 : KP1;
        #pragma unroll 1
        for (int d4 = 0; d4 < 16; d4++) {
            float4 qv[8];
            #pragma unroll
            for (int ii = 0; ii < 8; ii++)
                qv[ii] = *(const float4*)&Q[(i0 + ii) * DD + d4 * 4];
            if (jg == 0) {  // fold q.kpre into row-sum partials once
                float4 kp = *(const float4*)&KP[d4 * 4];
                #pragma unroll
                for (int ii = 0; ii < 8; ii++)
                    dq[ii] += qv[ii].x * kp.x + qv[ii].y * kp.y + qv[ii].z * kp.z + qv[ii].w * kp.w;
            }
            #pragma unroll
            for (int jj = 0; jj < 8; jj++) {
                float4 kv = *(const float4*)&K[(j0 + jj) * DD + d4 * 4];
                #pragma unroll
                for (int ii = 0; ii < 8; ii++)
                    acc[ii][jj] += qv[ii].x * kv.x + qv[ii].y * kv.y + qv[ii].z * kv.z + qv[ii].w * kv.w;
            }
        }
    }

    // ---- mask (tril), store T, emit denominator partials ----
    #pragma unroll
    for (int ii = 0; ii < 8; ii++) {
        const int i = i0 + ii;
        float ds = (jg == 0) ? dq[ii] : 0.f;
        float4 r0, r1;
        r0.x = (j0 + 0 <= i) ? acc[ii][0] : 0.f;
        r0.y = (j0 + 1 <= i) ? acc[ii][1] : 0.f;
        r0.z = (j0 + 2 <= i) ? acc[ii][2] : 0.f;
        r0.w = (j0 + 3 <= i) ? acc[ii][3] : 0.f;
        r1.x = (j0 + 4 <= i) ? acc[ii][4] : 0.f;
        r1.y = (j0 + 5 <= i) ? acc[ii][5] : 0.f;
        r1.z = (j0 + 6 <= i) ? acc[ii][6] : 0.f;
        r1.w = (j0 + 7 <= i) ? acc[ii][7] : 0.f;
        ds += r0.x + r0.y + r0.z + r0.w + r1.x + r1.y + r1.z + r1.w;
        *(float4*)&T[i * CC + j0]     = r0;
        *(float4*)&T[i * CC + j0 + 4] = r1;
        DEN[i * 16 + jg] = ds;
    }
    __syncthreads();

    // ---- overwrite X region with v, S1, S2; reduce denominator ----
    {
        const float4* vsrc = (const float4*)(vg + cbase);
        #pragma unroll
        for (int u = 0; u < 8; u++) {
            int idx = u * 256 + tid;
            ((float4*)V)[idx] = vsrc[idx];
        }
        const float4* s1src = (const float4*)&g_S[(((size_t)0 * G + g) * NC + c) * (size_t)(DD * EE)];
        const float4* s2src = (const float4*)&g_S[(((size_t)1 * G + g) * NC + c) * (size_t)(DD * EE)];
        #pragma unroll
        for (int u = 0; u < 4; u++) {
            int idx = u * 256 + tid;
            ((float4*)S1)[idx] = s1src[idx];
            ((float4*)S2)[idx] = s2src[idx];
        }
    }
    if (tid < CC) {
        float s = 0.f;
        #pragma unroll
        for (int p = 0; p < 16; p++) s += DEN[tid * 16 + p];
        DNV[tid] = 1.0f / (s + 1e-10f);
    }
    __syncthreads();

    // ---- Stage B: out = (tril(T)@v + q1@S1 + q2@S2) * dinv ----
    const int e0 = jg * 4;
    float a2[8][4];
    #pragma unroll
    for (int a = 0; a < 8; a++)
        #pragma unroll
        for (int b = 0; b < 4; b++) a2[a][b] = 0.f;

    #pragma unroll 1
    for (int j4 = 0; j4 < 32; j4++) {
        float4 v0 = *(const float4*)&V[(j4 * 4 + 0) * EE + e0];
        float4 v1 = *(const float4*)&V[(j4 * 4 + 1) * EE + e0];
        float4 v2 = *(const float4*)&V[(j4 * 4 + 2) * EE + e0];
        float4 v3 = *(const float4*)&V[(j4 * 4 + 3) * EE + e0];
        #pragma unroll
        for (int ii = 0; ii < 8; ii++) {
            float4 t = *(const float4*)&T[(i0 + ii) * CC + j4 * 4];
            a2[ii][0] += t.x * v0.x + t.y * v1.x + t.z * v2.x + t.w * v3.x;
            a2[ii][1] += t.x * v0.y + t.y * v1.y + t.z * v2.y + t.w * v3.y;
            a2[ii][2] += t.x * v0.z + t.y * v1.z + t.z * v2.z + t.w * v3.z;
            a2[ii][3] += t.x * v0.w + t.y * v1.w + t.z * v2.w + t.w * v3.w;
        }
    }
    #pragma unroll 1
    for (int m = 0; m < 2; m++) {
        const float* Q = m ? Q2 : Q1;
        const float* S = m ? S2 : S1;
        #pragma unroll 1
        for (int d4 = 0; d4 < 16; d4++) {
            float4 s0 = *(const float4*)&S[(d4 * 4 + 0) * EE + e0];
            float4 s1 = *(const float4*)&S[(d4 * 4 + 1) * EE + e0];
            float4 s2 = *(const float4*)&S[(d4 * 4 + 2) * EE + e0];
            float4 s3 = *(const float4*)&S[(d4 * 4 + 3) * EE + e0];
            #pragma unroll
            for (int ii = 0; ii < 8; ii++) {
                float4 qv = *(const float4*)&Q[(i0 + ii) * DD + d4 * 4];
                a2[ii][0] += qv.x * s0.x + qv.y * s1.x + qv.z * s2.x + qv.w * s3.x;
                a2[ii][1] += qv.x * s0.y + qv.y * s1.y + qv.z * s2.y + qv.w * s3.y;
                a2[ii][2] += qv.x * s0.z + qv.y * s1.z + qv.z * s2.z + qv.w * s3.z;
                a2[ii][3] += qv.x * s0.w + qv.y * s1.w + qv.z * s2.w + qv.w * s3.w;
            }
        }
    }

    float* op = outg + cbase;  // out layout == input layout, E == D
    #pragma unroll
    for (int ii = 0; ii < 8; ii++) {
        float di = DNV[i0 + ii];
        float4 r = make_float4(a2[ii][0] * di, a2[ii][1] * di, a2[ii][2] * di, a2[ii][3] * di);
        *(float4*)&op[(i0 + ii) * EE + e0] = r;
    }
}

// ---------------------------------------------------------------------------
extern "C" void kernel_launch(void* const* d_in, const int* in_sizes, int n_in,
                              void* d_out, int out_size) {
    const float* q  = (const float*)d_in[0];
    const float* k  = (const float*)d_in[1];
    const float* qr = (const float*)d_in[2];
    const float* kr = (const float*)d_in[3];
    const float* v  = (const float*)d_in[4];
    float* out = (float*)d_out;

    cudaFuncSetAttribute(pass1_kernel, cudaFuncAttributeMaxDynamicSharedMemorySize, 2 * CC * DD * 4);
    cudaFuncSetAttribute(pass3_kernel, cudaFuncAttributeMaxDynamicSharedMemorySize, SMEM3_BYTES);

    dim3 g1(NC, G, 2);
    pass1_kernel<<<g1, 256, 2 * CC * DD * 4>>>(k, kr, v);
    dim3 g2(G, 2);
    pass2_kernel<<<g2, 256>>>();
    dim3 g3(NC, G);
    pass3_kernel<<<g3, 256, SMEM3_BYTES>>>(q, qr, k, kr, v, out);
}